// round 11
// baseline (speedup 1.0000x reference)
#include <cuda_runtime.h>
#include <cuda_fp16.h>

typedef unsigned int uint;

// ---------------- scratch (device globals; no allocs allowed) ----------------
__device__ __half g_qh[2048L * 64 * 256];   // 64 MB  q hi (hi-only now)
__device__ __half g_kh[4096L * 64 * 256];   // 128 MB k hi
__device__ __half g_vh[4096L * 64 * 256];   // 128 MB v hi (seq-major)
__device__ __half g_wq[256 * 256];          // fp16 weights (pre-converted)
__device__ __half g_wkv[512 * 256];
__device__ __half g_wp[256 * 256];

#define DEV_INLINE __device__ __forceinline__

DEV_INLINE void mma16816f16(float* d, const uint* a, const uint* b) {
    asm volatile(
        "mma.sync.aligned.m16n8k16.row.col.f32.f16.f16.f32 "
        "{%0,%1,%2,%3}, {%4,%5,%6,%7}, {%8,%9}, {%0,%1,%2,%3};\n"
        : "+f"(d[0]), "+f"(d[1]), "+f"(d[2]), "+f"(d[3])
        : "r"(a[0]), "r"(a[1]), "r"(a[2]), "r"(a[3]), "r"(b[0]), "r"(b[1]));
}

DEV_INLINE uint lds_u32(const void* p) { return *reinterpret_cast<const uint*>(p); }

DEV_INLINE uint sm_u32(const void* p) {
    uint a;
    asm("{ .reg .u64 t; cvta.to.shared.u64 t, %1; cvt.u32.u64 %0, t; }" : "=r"(a) : "l"(p));
    return a;
}

#define CP16(dst, src) \
    asm volatile("cp.async.cg.shared.global [%0], [%1], 16;" :: "r"(dst), "l"(src))
#define CP_COMMIT() asm volatile("cp.async.commit_group;" ::: "memory")
#define CP_WAIT(n)  asm volatile("cp.async.wait_group %0;" :: "n"(n) : "memory")

DEV_INLINE void ldsm_x4(uint* r, uint a) {
    asm volatile("ldmatrix.sync.aligned.m8n8.x4.shared.b16 {%0,%1,%2,%3}, [%4];"
                 : "=r"(r[0]), "=r"(r[1]), "=r"(r[2]), "=r"(r[3]) : "r"(a));
}
DEV_INLINE void ldsm_x2(uint* r, uint a) {
    asm volatile("ldmatrix.sync.aligned.m8n8.x2.shared.b16 {%0,%1}, [%2];"
                 : "=r"(r[0]), "=r"(r[1]) : "r"(a));
}
DEV_INLINE void ldsm_x2t(uint* r, uint a) {
    asm volatile("ldmatrix.sync.aligned.m8n8.x2.trans.shared.b16 {%0,%1}, [%2];"
                 : "=r"(r[0]), "=r"(r[1]) : "r"(a));
}

DEV_INLINE void packsplit_h(float x, float y, uint& hi, uint& lo) {
    __half2 h = __floats2half2_rn(x, y);
    __half2 l = __floats2half2_rn(x - __half2float(__low2half(h)),
                                  y - __half2float(__high2half(h)));
    hi = *reinterpret_cast<uint*>(&h);
    lo = *reinterpret_cast<uint*>(&l);
}

DEV_INLINE uint pack_h(float x, float y) {
    __half2 h = __floats2half2_rn(x, y);
    return *reinterpret_cast<uint*>(&h);
}

// =============================================================================
// weight pre-convert: fp32 -> fp16 (one shot)
// =============================================================================
__global__ __launch_bounds__(256) void wconv_kernel(
    const float* __restrict__ qw, const float* __restrict__ kvw,
    const float* __restrict__ pw)
{
    int i = (blockIdx.x * 256 + threadIdx.x) * 4;
    if (i < 65536) {
        float4 v = *reinterpret_cast<const float4*>(qw + i);
        uint2 o; o.x = pack_h(v.x, v.y); o.y = pack_h(v.z, v.w);
        *reinterpret_cast<uint2*>(g_wq + i) = o;
    }
    if (i < 131072) {
        float4 v = *reinterpret_cast<const float4*>(kvw + i);
        uint2 o; o.x = pack_h(v.x, v.y); o.y = pack_h(v.z, v.w);
        *reinterpret_cast<uint2*>(g_wkv + i) = o;
    }
    if (i < 65536) {
        float4 v = *reinterpret_cast<const float4*>(pw + i);
        uint2 o; o.x = pack_h(v.x, v.y); o.y = pack_h(v.z, v.w);
        *reinterpret_cast<uint2*>(g_wp + i) = o;
    }
}

// =============================================================================
// hi-only GEMM (serves q and kv): C = round16( A[M,256] @ Bw^T + bias ).
// A fp32 reg-pipelined; B fp16 cp.async. occ 2. Col<256 -> C1 else C2.
// (R10 gemm_kv_kernel, proven)
// =============================================================================
__global__ __launch_bounds__(256, 2) void gemm_h_kernel(
    const float* __restrict__ A, const __half* __restrict__ Bw,
    const float* __restrict__ bias, __half* __restrict__ C1,
    __half* __restrict__ C2)
{
    constexpr int K = 256, LDT = 40, STG_H = 10240;
    extern __shared__ __half smh[];
    const uint sb = sm_u32(smh);
    const int tid = threadIdx.x;
    const int m0 = blockIdx.y * 128, n0 = blockIdx.x * 128;
    const int lr = tid >> 3, lc = (tid & 7) << 2;

    float4 va0[4], va1[4];
    auto ldg_a = [&](int kt, float4 (&va)[4]) {
        int k0 = kt * 32;
        #pragma unroll
        for (int u = 0; u < 4; u++) {
            int r = lr + u * 32;
            va[u] = *reinterpret_cast<const float4*>(A + (size_t)(m0 + r) * K + k0 + lc);
        }
    };
    auto sts_a = [&](int s, const float4 (&va)[4]) {
        __half* st = smh + s * STG_H;
        #pragma unroll
        for (int u = 0; u < 4; u++) {
            int r = lr + u * 32;
            __half* hp = st + r * LDT + lc;
            *reinterpret_cast<__half2*>(hp) = __floats2half2_rn(va[u].x, va[u].y);
            *reinterpret_cast<__half2*>(hp + 2) = __floats2half2_rn(va[u].z, va[u].w);
        }
    };
    auto cp_b = [&](int kt, int s) {
        int k0 = kt * 32;
        #pragma unroll
        for (int u = 0; u < 2; u++) {
            int f = tid + u * 256;
            int r = f >> 2, c = (f & 3) << 3;
            uint dst = sb + (uint)(s * STG_H + 5120 + r * LDT + c) * 2;
            CP16(dst, Bw + (size_t)(n0 + r) * K + k0 + c);
        }
        CP_COMMIT();
    };

    const int warp = tid >> 5, lane = tid & 31;
    const int wm = warp & 3, wn = warp >> 2;
    const int g = lane >> 2, tc = lane & 3;

    float acc[2][8][4];
    #pragma unroll
    for (int i = 0; i < 2; i++)
        #pragma unroll
        for (int j = 0; j < 8; j++)
            #pragma unroll
            for (int e = 0; e < 4; e++) acc[i][j][e] = 0.f;

    cp_b(0, 0);
    cp_b(1, 1);
    ldg_a(0, va0);
    sts_a(0, va0);
    ldg_a(1, va1);
    CP_WAIT(0);
    __syncthreads();

    #pragma unroll
    for (int kt = 0; kt < 8; kt++) {
        if (kt < 6) {
            if ((kt & 1) == 0) ldg_a(kt + 2, va0);
            else               ldg_a(kt + 2, va1);
        }
        const __half* st = smh + (kt & 1) * STG_H;
        const __half* Ah = st;
        const __half* Bh = st + 5120;

        #pragma unroll
        for (int kk = 0; kk < 2; kk++) {
            const int kc = kk * 16 + tc * 2;
            uint ah[2][4];
            #pragma unroll
            for (int mi = 0; mi < 2; mi++) {
                int row = wm * 32 + mi * 16 + g;
                ah[mi][0] = lds_u32(Ah + row * LDT + kc);
                ah[mi][1] = lds_u32(Ah + (row + 8) * LDT + kc);
                ah[mi][2] = lds_u32(Ah + row * LDT + kc + 8);
                ah[mi][3] = lds_u32(Ah + (row + 8) * LDT + kc + 8);
            }
            #pragma unroll
            for (int nj = 0; nj < 8; nj++) {
                int n = wn * 64 + nj * 8 + g;
                uint bh[2];
                bh[0] = lds_u32(Bh + n * LDT + kc);
                bh[1] = lds_u32(Bh + n * LDT + kc + 8);
                #pragma unroll
                for (int mi = 0; mi < 2; mi++)
                    mma16816f16(acc[mi][nj], ah[mi], bh);
            }
        }
        __syncthreads();
        if (kt < 6) cp_b(kt + 2, kt & 1);
        if (kt < 7) {
            if (((kt + 1) & 1) == 0) sts_a((kt + 1) & 1, va0);
            else                     sts_a((kt + 1) & 1, va1);
            if (kt < 6) { CP_WAIT(1); } else { CP_WAIT(0); }
            __syncthreads();
        }
    }

    #pragma unroll
    for (int mi = 0; mi < 2; mi++) {
        #pragma unroll
        for (int nj = 0; nj < 8; nj++) {
            int row = m0 + wm * 32 + mi * 16 + g;
            int col = n0 + wn * 64 + nj * 8 + tc * 2;
            float b0 = __ldg(bias + col), b1 = __ldg(bias + col + 1);
            __half* dst = (col < 256) ? C1 : C2;
            int cc = (col < 256) ? col : col - 256;
            *reinterpret_cast<uint*>(dst + (size_t)row * 256 + cc) =
                pack_h(acc[mi][nj][0] + b0, acc[mi][nj][1] + b1);
            *reinterpret_cast<uint*>(dst + (size_t)(row + 8) * 256 + cc) =
                pack_h(acc[mi][nj][2] + b0, acc[mi][nj][3] + b1);
        }
    }
}

// =============================================================================
// Fused attention + proj. One CTA per bt (4096 CTAs), 512 threads = 16 warps.
// Attention: 2 warps/head x 8 heads; O kept in smem; proj (O @ wp^T + pb)
// computed in-kernel with wp streamed fp16 via cp.async double buffer.
// smem (bytes): QH 0 | KH 33792 | VH 67584 | OS 101376 | WB 135168 (2x20480)
//               | rpb 176128 (7200). total 183328 -> occ 1 (16 warps).
// =============================================================================
__global__ __launch_bounds__(512, 1) void attn_proj_kernel(
    const float* __restrict__ rpb, const __half* __restrict__ wp,
    const float* __restrict__ pb, float* __restrict__ out)
{
    constexpr int LDO = 264;          // row stride (halves) for 256-wide tiles
    extern __shared__ char smc[];
    const uint sb = sm_u32(smc);
    const uint QH = sb, KH = sb + 33792, VH = sb + 67584;
    const uint OS = sb + 101376, WB = sb + 135168;
    float* srpb = reinterpret_cast<float*>(smc + 176128);

    const int tid = threadIdx.x;
    const int bt = blockIdx.x;
    const int b = bt >> 1;

    const __half* qh_src = g_qh + (size_t)b * (64 * 256);
    const __half* kh_src = g_kh + (size_t)bt * (64 * 256);
    const __half* vh_src = g_vh + (size_t)bt * (64 * 256);

    auto cp_wp = [&](int kc, int s) {
        #pragma unroll
        for (int u = 0; u < 2; u++) {
            int f = tid + u * 512;            // 0..1023
            int r = f >> 2, c = (f & 3) << 3;
            CP16(WB + (uint)(s * 20480 + (r * 40 + c) * 2),
                 wp + (size_t)r * 256 + kc * 32 + c);
        }
        CP_COMMIT();
    };

    // ---- group A: q/k/v tiles (64 x 256 halves each) + rpb ----
    #pragma unroll
    for (int u = 0; u < 4; u++) {
        int f = tid + u * 512;                // 0..2047
        int r = f >> 5, cc = (f & 31) << 3;
        uint doff = (uint)(r * LDO + cc) * 2;
        size_t soff = (size_t)r * 256 + cc;
        CP16(QH + doff, qh_src + soff);
        CP16(KH + doff, kh_src + soff);
        CP16(VH + doff, vh_src + soff);
    }
    if (tid < 450) CP16(sb + 176128 + tid * 16, rpb + tid * 4);
    CP_COMMIT();
    // ---- groups B, C: wp chunks 0, 1 ----
    cp_wp(0, 0);
    cp_wp(1, 1);
    CP_WAIT(2);                               // group A done
    __syncthreads();

    const int warp = tid >> 5, lane = tid & 31;
    const int h = warp >> 1;                  // head 0..7
    const int half = warp & 1;
    const int g = lane >> 2, tc = lane & 3;
    const int r0 = half * 32;

    // ---- S = qh @ kh^T (32 x 64, hi-only) ----
    float S[2][8][4];
    #pragma unroll
    for (int i = 0; i < 2; i++)
        #pragma unroll
        for (int j = 0; j < 8; j++)
            #pragma unroll
            for (int e = 0; e < 4; e++) S[i][j][e] = 0.f;

    #pragma unroll
    for (int kk = 0; kk < 2; kk++) {
        const int kc0 = h * 32 + kk * 16;
        uint ah[2][4];
        #pragma unroll
        for (int mi = 0; mi < 2; mi++) {
            int arow = r0 + mi * 16 + (lane & 15);
            int acol = kc0 + (lane >> 4) * 8;
            ldsm_x4(ah[mi], QH + (uint)(arow * LDO + acol) * 2);
        }
        #pragma unroll
        for (int nj = 0; nj < 8; nj++) {
            int brow = nj * 8 + (lane & 7);
            int bcol = kc0 + ((lane >> 3) & 1) * 8;
            uint bh[2];
            ldsm_x2(bh, KH + (uint)(brow * LDO + bcol) * 2);
            #pragma unroll
            for (int mi = 0; mi < 2; mi++)
                mma16816f16(S[mi][nj], ah[mi], bh);
        }
    }

    // ---- scale + relative-position bias + softmax (fp32) ----
    const float scale = 0.17677669529663687f;
    #pragma unroll
    for (int mi = 0; mi < 2; mi++) {
        #pragma unroll
        for (int p = 0; p < 2; p++) {
            int row = r0 + mi * 16 + g + p * 8;
            int pi = row >> 3, pj = row & 7;
            float mx = -1e30f;
            #pragma unroll
            for (int nj = 0; nj < 8; nj++) {
                #pragma unroll
                for (int e = 0; e < 2; e++) {
                    int col = nj * 8 + tc * 2 + e;
                    int qi = col >> 3, qj = col & 7;
                    int rel = (pi - qi + 7) * 15 + (pj - qj + 7);
                    float s = S[mi][nj][p * 2 + e] * scale + srpb[rel * 8 + h];
                    S[mi][nj][p * 2 + e] = s;
                    mx = fmaxf(mx, s);
                }
            }
            mx = fmaxf(mx, __shfl_xor_sync(0xffffffffu, mx, 1));
            mx = fmaxf(mx, __shfl_xor_sync(0xffffffffu, mx, 2));
            float sum = 0.f;
            #pragma unroll
            for (int nj = 0; nj < 8; nj++) {
                #pragma unroll
                for (int e = 0; e < 2; e++) {
                    float pe = __expf(S[mi][nj][p * 2 + e] - mx);
                    S[mi][nj][p * 2 + e] = pe;
                    sum += pe;
                }
            }
            sum += __shfl_xor_sync(0xffffffffu, sum, 1);
            sum += __shfl_xor_sync(0xffffffffu, sum, 2);
            float inv = 1.f / sum;
            #pragma unroll
            for (int nj = 0; nj < 8; nj++) {
                S[mi][nj][p * 2 + 0] *= inv;
                S[mi][nj][p * 2 + 1] *= inv;
            }
        }
    }

    // ---- pack P to fp16 hi/lo ----
    uint phi[2][8][2], plo[2][8][2];
    #pragma unroll
    for (int mi = 0; mi < 2; mi++)
        #pragma unroll
        for (int nj = 0; nj < 8; nj++) {
            packsplit_h(S[mi][nj][0], S[mi][nj][1], phi[mi][nj][0], plo[mi][nj][0]);
            packsplit_h(S[mi][nj][2], S[mi][nj][3], phi[mi][nj][1], plo[mi][nj][1]);
        }

    // ---- O = (Ph + Pl) @ Vh  (V frags via ldmatrix.trans) ----
    float O[2][4][4];
    #pragma unroll
    for (int i = 0; i < 2; i++)
        #pragma unroll
        for (int j = 0; j < 4; j++)
            #pragma unroll
            for (int e = 0; e < 4; e++) O[i][j][e] = 0.f;

    #pragma unroll
    for (int t = 0; t < 4; t++) {
        #pragma unroll
        for (int jn = 0; jn < 4; jn++) {
            int vrow = t * 16 + (lane & 7) + ((lane >> 3) & 1) * 8;
            int vcol = h * 32 + jn * 8;
            uint bh[2];
            ldsm_x2t(bh, VH + (uint)(vrow * LDO + vcol) * 2);
            #pragma unroll
            for (int mi = 0; mi < 2; mi++) {
                uint pa[4] = {phi[mi][2 * t][0], phi[mi][2 * t][1],
                              phi[mi][2 * t + 1][0], phi[mi][2 * t + 1][1]};
                uint la[4] = {plo[mi][2 * t][0], plo[mi][2 * t][1],
                              plo[mi][2 * t + 1][0], plo[mi][2 * t + 1][1]};
                mma16816f16(O[mi][jn], pa, bh);
                mma16816f16(O[mi][jn], la, bh);
            }
        }
    }

    // ---- O -> smem (fp16 hi) ----
    __half* osp = reinterpret_cast<__half*>(smc + 101376);
    #pragma unroll
    for (int mi = 0; mi < 2; mi++) {
        #pragma unroll
        for (int jn = 0; jn < 4; jn++) {
            int row = r0 + mi * 16 + g;
            int col = h * 32 + jn * 8 + tc * 2;
            *reinterpret_cast<uint*>(osp + row * LDO + col) =
                pack_h(O[mi][jn][0], O[mi][jn][1]);
            *reinterpret_cast<uint*>(osp + (row + 8) * LDO + col) =
                pack_h(O[mi][jn][2], O[mi][jn][3]);
        }
    }
    CP_WAIT(0);                               // wp chunks 0,1 landed
    __syncthreads();

    // ---- proj: out = O @ wp^T + pb.  16 warps = 2m x 8n, warp tile 32x32 ----
    const int wm2 = warp & 1, wn2 = warp >> 1;
    float pacc[2][4][4];
    #pragma unroll
    for (int i = 0; i < 2; i++)
        #pragma unroll
        for (int j = 0; j < 4; j++)
            #pragma unroll
            for (int e = 0; e < 4; e++) pacc[i][j][e] = 0.f;

    #pragma unroll
    for (int kc = 0; kc < 8; kc++) {
        const uint wbs = WB + (uint)((kc & 1) * 20480);
        #pragma unroll
        for (int kk = 0; kk < 2; kk++) {
            uint ah[2][4];
            #pragma unroll
            for (int mi = 0; mi < 2; mi++) {
                int arow = wm2 * 32 + mi * 16 + (lane & 15);
                int acol = kc * 32 + kk * 16 + (lane >> 4) * 8;
                ldsm_x4(ah[mi], OS + (uint)(arow * LDO + acol) * 2);
            }
            #pragma unroll
            for (int nj = 0; nj < 4; nj++) {
                int brow = wn2 * 32 + nj * 8 + (lane & 7);
                int bcol = kk * 16 + ((lane >> 3) & 1) * 8;
                uint bh[2];
                ldsm_x2(bh, wbs + (uint)(brow * 40 + bcol) * 2);
                #pragma unroll
                for (int mi = 0; mi < 2; mi++)
                    mma16816f16(pacc[mi][nj], ah[mi], bh);
            }
        }
        if (kc < 6) {
            __syncthreads();                  // all warps done with stage kc&1
            cp_wp(kc + 2, kc & 1);
            CP_WAIT(1);                       // chunk kc+1 resident
            __syncthreads();
        } else if (kc == 6) {
            CP_WAIT(0);                       // chunk 7 resident
            __syncthreads();
        }
    }

    // ---- epilogue: fp32 out ----
    float* dst = out + (size_t)bt * (64 * 256);
    #pragma unroll
    for (int mi = 0; mi < 2; mi++) {
        #pragma unroll
        for (int nj = 0; nj < 4; nj++) {
            int row = wm2 * 32 + mi * 16 + g;
            int col = wn2 * 32 + nj * 8 + tc * 2;
            float b0 = __ldg(pb + col), b1 = __ldg(pb + col + 1);
            *reinterpret_cast<float2*>(dst + row * 256 + col) =
                make_float2(pacc[mi][nj][0] + b0, pacc[mi][nj][1] + b1);
            *reinterpret_cast<float2*>(dst + (row + 8) * 256 + col) =
                make_float2(pacc[mi][nj][2] + b0, pacc[mi][nj][3] + b1);
        }
    }
}

// =============================================================================
extern "C" void kernel_launch(void* const* d_in, const int* in_sizes, int n_in,
                              void* d_out, int out_size)
{
    const float* x      = (const float*)d_in[0];
    const float* memory = (const float*)d_in[1];
    const float* q_w    = (const float*)d_in[2];
    const float* q_b    = (const float*)d_in[3];
    const float* kv_w   = (const float*)d_in[4];
    const float* kv_b   = (const float*)d_in[5];
    const float* proj_w = (const float*)d_in[6];
    const float* proj_b = (const float*)d_in[7];
    const float* rpb    = (const float*)d_in[8];
    float* out = (float*)d_out;

    __half *qh, *kh, *vh, *wq, *wkv, *wp;
    cudaGetSymbolAddress((void**)&qh, g_qh);
    cudaGetSymbolAddress((void**)&kh, g_kh);
    cudaGetSymbolAddress((void**)&vh, g_vh);
    cudaGetSymbolAddress((void**)&wq, g_wq);
    cudaGetSymbolAddress((void**)&wkv, g_wkv);
    cudaGetSymbolAddress((void**)&wp, g_wp);

    cudaFuncSetAttribute(gemm_h_kernel,
                         cudaFuncAttributeMaxDynamicSharedMemorySize, 40960);
    cudaFuncSetAttribute(attn_proj_kernel,
                         cudaFuncAttributeMaxDynamicSharedMemorySize, 183328);

    // pre-convert weights to fp16
    wconv_kernel<<<128, 256>>>(q_w, kv_w, proj_w);
    // q projection (hi-only) -> qh
    gemm_h_kernel<<<dim3(2, 1024), 256, 40960>>>(x, wq, q_b, qh, qh);
    // kv projection (hi-only) -> kh, vh
    gemm_h_kernel<<<dim3(4, 2048), 256, 40960>>>(memory, wkv, kv_b, kh, vh);
    // fused attention + output projection
    attn_proj_kernel<<<4096, 512, 183328>>>(rpb, wp, proj_b, out);
}

// round 12
// speedup vs baseline: 1.5444x; 1.5444x over previous
#include <cuda_runtime.h>
#include <cuda_fp16.h>

typedef unsigned int uint;

// ---------------- scratch (device globals; no allocs allowed) ----------------
__device__ __half g_qh[2048L * 64 * 256];   // 64 MB  q hi (hi-only)
__device__ __half g_kh[4096L * 64 * 256];   // 128 MB k hi
__device__ __half g_vh[4096L * 64 * 256];   // 128 MB v hi (seq-major)
__device__ __half g_oh[4096L * 64 * 256];   // 128 MB attention out (hi only)
__device__ __half g_wq[256 * 256];          // fp16 weights (pre-converted)
__device__ __half g_wkv[512 * 256];
__device__ __half g_wp[256 * 256];

#define DEV_INLINE __device__ __forceinline__

DEV_INLINE void mma16816f16(float* d, const uint* a, const uint* b) {
    asm volatile(
        "mma.sync.aligned.m16n8k16.row.col.f32.f16.f16.f32 "
        "{%0,%1,%2,%3}, {%4,%5,%6,%7}, {%8,%9}, {%0,%1,%2,%3};\n"
        : "+f"(d[0]), "+f"(d[1]), "+f"(d[2]), "+f"(d[3])
        : "r"(a[0]), "r"(a[1]), "r"(a[2]), "r"(a[3]), "r"(b[0]), "r"(b[1]));
}

DEV_INLINE uint lds_u32(const void* p) { return *reinterpret_cast<const uint*>(p); }

DEV_INLINE uint sm_u32(const void* p) {
    uint a;
    asm("{ .reg .u64 t; cvta.to.shared.u64 t, %1; cvt.u32.u64 %0, t; }" : "=r"(a) : "l"(p));
    return a;
}

#define CP16(dst, src) \
    asm volatile("cp.async.cg.shared.global [%0], [%1], 16;" :: "r"(dst), "l"(src))
#define CP_COMMIT() asm volatile("cp.async.commit_group;" ::: "memory")
#define CP_WAIT(n)  asm volatile("cp.async.wait_group %0;" :: "n"(n) : "memory")

DEV_INLINE void ldsm_x4(uint* r, uint a) {
    asm volatile("ldmatrix.sync.aligned.m8n8.x4.shared.b16 {%0,%1,%2,%3}, [%4];"
                 : "=r"(r[0]), "=r"(r[1]), "=r"(r[2]), "=r"(r[3]) : "r"(a));
}
DEV_INLINE void ldsm_x2(uint* r, uint a) {
    asm volatile("ldmatrix.sync.aligned.m8n8.x2.shared.b16 {%0,%1}, [%2];"
                 : "=r"(r[0]), "=r"(r[1]) : "r"(a));
}
DEV_INLINE void ldsm_x2t(uint* r, uint a) {
    asm volatile("ldmatrix.sync.aligned.m8n8.x2.trans.shared.b16 {%0,%1}, [%2];"
                 : "=r"(r[0]), "=r"(r[1]) : "r"(a));
}

DEV_INLINE void packsplit_h(float x, float y, uint& hi, uint& lo) {
    __half2 h = __floats2half2_rn(x, y);
    __half2 l = __floats2half2_rn(x - __half2float(__low2half(h)),
                                  y - __half2float(__high2half(h)));
    hi = *reinterpret_cast<uint*>(&h);
    lo = *reinterpret_cast<uint*>(&l);
}

DEV_INLINE uint pack_h(float x, float y) {
    __half2 h = __floats2half2_rn(x, y);
    return *reinterpret_cast<uint*>(&h);
}

// =============================================================================
// weight pre-convert: fp32 -> fp16 (one shot)
// =============================================================================
__global__ __launch_bounds__(256) void wconv_kernel(
    const float* __restrict__ qw, const float* __restrict__ kvw,
    const float* __restrict__ pw)
{
    int i = (blockIdx.x * 256 + threadIdx.x) * 4;
    if (i < 65536) {
        float4 v = *reinterpret_cast<const float4*>(qw + i);
        uint2 o; o.x = pack_h(v.x, v.y); o.y = pack_h(v.z, v.w);
        *reinterpret_cast<uint2*>(g_wq + i) = o;
    }
    if (i < 131072) {
        float4 v = *reinterpret_cast<const float4*>(kvw + i);
        uint2 o; o.x = pack_h(v.x, v.y); o.y = pack_h(v.z, v.w);
        *reinterpret_cast<uint2*>(g_wkv + i) = o;
    }
    if (i < 65536) {
        float4 v = *reinterpret_cast<const float4*>(pw + i);
        uint2 o; o.x = pack_h(v.x, v.y); o.y = pack_h(v.z, v.w);
        *reinterpret_cast<uint2*>(g_wp + i) = o;
    }
}

// =============================================================================
// hi-only GEMM (serves q and kv): C = round16( A[M,256] @ Bw^T + bias ).
// A fp32 reg-pipelined; B fp16 cp.async. occ 2. Col<256 -> C1 else C2.
// (R10 proven)
// =============================================================================
__global__ __launch_bounds__(256, 2) void gemm_h_kernel(
    const float* __restrict__ A, const __half* __restrict__ Bw,
    const float* __restrict__ bias, __half* __restrict__ C1,
    __half* __restrict__ C2)
{
    constexpr int K = 256, LDT = 40, STG_H = 10240;
    extern __shared__ __half smh[];
    const uint sb = sm_u32(smh);
    const int tid = threadIdx.x;
    const int m0 = blockIdx.y * 128, n0 = blockIdx.x * 128;
    const int lr = tid >> 3, lc = (tid & 7) << 2;

    float4 va0[4], va1[4];
    auto ldg_a = [&](int kt, float4 (&va)[4]) {
        int k0 = kt * 32;
        #pragma unroll
        for (int u = 0; u < 4; u++) {
            int r = lr + u * 32;
            va[u] = *reinterpret_cast<const float4*>(A + (size_t)(m0 + r) * K + k0 + lc);
        }
    };
    auto sts_a = [&](int s, const float4 (&va)[4]) {
        __half* st = smh + s * STG_H;
        #pragma unroll
        for (int u = 0; u < 4; u++) {
            int r = lr + u * 32;
            __half* hp = st + r * LDT + lc;
            *reinterpret_cast<__half2*>(hp) = __floats2half2_rn(va[u].x, va[u].y);
            *reinterpret_cast<__half2*>(hp + 2) = __floats2half2_rn(va[u].z, va[u].w);
        }
    };
    auto cp_b = [&](int kt, int s) {
        int k0 = kt * 32;
        #pragma unroll
        for (int u = 0; u < 2; u++) {
            int f = tid + u * 256;
            int r = f >> 2, c = (f & 3) << 3;
            uint dst = sb + (uint)(s * STG_H + 5120 + r * LDT + c) * 2;
            CP16(dst, Bw + (size_t)(n0 + r) * K + k0 + c);
        }
        CP_COMMIT();
    };

    const int warp = tid >> 5, lane = tid & 31;
    const int wm = warp & 3, wn = warp >> 2;
    const int g = lane >> 2, tc = lane & 3;

    float acc[2][8][4];
    #pragma unroll
    for (int i = 0; i < 2; i++)
        #pragma unroll
        for (int j = 0; j < 8; j++)
            #pragma unroll
            for (int e = 0; e < 4; e++) acc[i][j][e] = 0.f;

    cp_b(0, 0);
    cp_b(1, 1);
    ldg_a(0, va0);
    sts_a(0, va0);
    ldg_a(1, va1);
    CP_WAIT(0);
    __syncthreads();

    #pragma unroll
    for (int kt = 0; kt < 8; kt++) {
        if (kt < 6) {
            if ((kt & 1) == 0) ldg_a(kt + 2, va0);
            else               ldg_a(kt + 2, va1);
        }
        const __half* st = smh + (kt & 1) * STG_H;
        const __half* Ah = st;
        const __half* Bh = st + 5120;

        #pragma unroll
        for (int kk = 0; kk < 2; kk++) {
            const int kc = kk * 16 + tc * 2;
            uint ah[2][4];
            #pragma unroll
            for (int mi = 0; mi < 2; mi++) {
                int row = wm * 32 + mi * 16 + g;
                ah[mi][0] = lds_u32(Ah + row * LDT + kc);
                ah[mi][1] = lds_u32(Ah + (row + 8) * LDT + kc);
                ah[mi][2] = lds_u32(Ah + row * LDT + kc + 8);
                ah[mi][3] = lds_u32(Ah + (row + 8) * LDT + kc + 8);
            }
            #pragma unroll
            for (int nj = 0; nj < 8; nj++) {
                int n = wn * 64 + nj * 8 + g;
                uint bh[2];
                bh[0] = lds_u32(Bh + n * LDT + kc);
                bh[1] = lds_u32(Bh + n * LDT + kc + 8);
                #pragma unroll
                for (int mi = 0; mi < 2; mi++)
                    mma16816f16(acc[mi][nj], ah[mi], bh);
            }
        }
        __syncthreads();
        if (kt < 6) cp_b(kt + 2, kt & 1);
        if (kt < 7) {
            if (((kt + 1) & 1) == 0) sts_a((kt + 1) & 1, va0);
            else                     sts_a((kt + 1) & 1, va1);
            if (kt < 6) { CP_WAIT(1); } else { CP_WAIT(0); }
            __syncthreads();
        }
    }

    #pragma unroll
    for (int mi = 0; mi < 2; mi++) {
        #pragma unroll
        for (int nj = 0; nj < 8; nj++) {
            int row = m0 + wm * 32 + mi * 16 + g;
            int col = n0 + wn * 64 + nj * 8 + tc * 2;
            float b0 = __ldg(bias + col), b1 = __ldg(bias + col + 1);
            __half* dst = (col < 256) ? C1 : C2;
            int cc = (col < 256) ? col : col - 256;
            *reinterpret_cast<uint*>(dst + (size_t)row * 256 + cc) =
                pack_h(acc[mi][nj][0] + b0, acc[mi][nj][1] + b1);
            *reinterpret_cast<uint*>(dst + (size_t)(row + 8) * 256 + cc) =
                pack_h(acc[mi][nj][2] + b0, acc[mi][nj][3] + b1);
        }
    }
}

// =============================================================================
// Fused attention (hi-only q; fp16 in via cp.async + ldmatrix). O hi-only out.
// One CTA per (bt, head-group of 4). 256 threads, smem 59424 B -> 2 CTAs/SM.
// smem: QH 0 | KH 17408 | VH 34816 | rpb 52224 (7200 B)
// =============================================================================
__global__ __launch_bounds__(256, 2) void attn_kernel(const float* __restrict__ rpb)
{
    extern __shared__ char smc[];
    const uint sb = sm_u32(smc);
    const uint QH = sb, KH = sb + 17408, VH = sb + 34816;
    float* srpb = reinterpret_cast<float*>(smc + 52224);

    const int tid = threadIdx.x;
    const int bt = blockIdx.x >> 1;
    const int hg = blockIdx.x & 1;
    const int b = bt >> 1;

    const __half* qh_src = g_qh + (size_t)b * (64 * 256) + hg * 128;
    const __half* kh_src = g_kh + (size_t)bt * (64 * 256) + hg * 128;
    const __half* vh_src = g_vh + (size_t)bt * (64 * 256) + hg * 128;

    #pragma unroll
    for (int u = 0; u < 4; u++) {
        int f = tid + u * 256;
        int r = f >> 4;
        int cc = (f & 15) << 3;
        uint doff = (uint)(r * 136 + cc) * 2;
        size_t soff = (size_t)r * 256 + cc;
        CP16(QH + doff, qh_src + soff);
        CP16(KH + doff, kh_src + soff);
        CP16(VH + doff, vh_src + soff);
    }
    for (int i = tid; i < 450; i += 256)
        CP16(sb + 52224 + i * 16, rpb + i * 4);
    CP_COMMIT();
    CP_WAIT(0);
    __syncthreads();

    const int warp = tid >> 5, lane = tid & 31;
    const int hl = warp >> 1;
    const int h = hg * 4 + hl;
    const int half = warp & 1;
    const int g = lane >> 2, tc = lane & 3;
    const int r0 = half * 32;

    // ---- S = qh @ kh^T (hi-only) ----
    float S[2][8][4];
    #pragma unroll
    for (int i = 0; i < 2; i++)
        #pragma unroll
        for (int j = 0; j < 8; j++)
            #pragma unroll
            for (int e = 0; e < 4; e++) S[i][j][e] = 0.f;

    #pragma unroll
    for (int kk = 0; kk < 2; kk++) {
        const int kc0 = hl * 32 + kk * 16;
        uint ah[2][4];
        #pragma unroll
        for (int mi = 0; mi < 2; mi++) {
            int arow = r0 + mi * 16 + (lane & 15);
            int acol = kc0 + (lane >> 4) * 8;
            ldsm_x4(ah[mi], QH + (uint)(arow * 136 + acol) * 2);
        }
        #pragma unroll
        for (int nj = 0; nj < 8; nj++) {
            int brow = nj * 8 + (lane & 7);
            int bcol = kc0 + ((lane >> 3) & 1) * 8;
            uint bh[2];
            ldsm_x2(bh, KH + (uint)(brow * 136 + bcol) * 2);
            #pragma unroll
            for (int mi = 0; mi < 2; mi++)
                mma16816f16(S[mi][nj], ah[mi], bh);
        }
    }

    // ---- scale + relative-position bias + softmax (fp32) ----
    const float scale = 0.17677669529663687f;
    #pragma unroll
    for (int mi = 0; mi < 2; mi++) {
        #pragma unroll
        for (int p = 0; p < 2; p++) {
            int row = r0 + mi * 16 + g + p * 8;
            int pi = row >> 3, pj = row & 7;
            float mx = -1e30f;
            #pragma unroll
            for (int nj = 0; nj < 8; nj++) {
                #pragma unroll
                for (int e = 0; e < 2; e++) {
                    int col = nj * 8 + tc * 2 + e;
                    int qi = col >> 3, qj = col & 7;
                    int rel = (pi - qi + 7) * 15 + (pj - qj + 7);
                    float s = S[mi][nj][p * 2 + e] * scale + srpb[rel * 8 + h];
                    S[mi][nj][p * 2 + e] = s;
                    mx = fmaxf(mx, s);
                }
            }
            mx = fmaxf(mx, __shfl_xor_sync(0xffffffffu, mx, 1));
            mx = fmaxf(mx, __shfl_xor_sync(0xffffffffu, mx, 2));
            float sum = 0.f;
            #pragma unroll
            for (int nj = 0; nj < 8; nj++) {
                #pragma unroll
                for (int e = 0; e < 2; e++) {
                    float pe = __expf(S[mi][nj][p * 2 + e] - mx);
                    S[mi][nj][p * 2 + e] = pe;
                    sum += pe;
                }
            }
            sum += __shfl_xor_sync(0xffffffffu, sum, 1);
            sum += __shfl_xor_sync(0xffffffffu, sum, 2);
            float inv = 1.f / sum;
            #pragma unroll
            for (int nj = 0; nj < 8; nj++) {
                S[mi][nj][p * 2 + 0] *= inv;
                S[mi][nj][p * 2 + 1] *= inv;
            }
        }
    }

    // ---- pack P to fp16 hi/lo ----
    uint phi[2][8][2], plo[2][8][2];
    #pragma unroll
    for (int mi = 0; mi < 2; mi++)
        #pragma unroll
        for (int nj = 0; nj < 8; nj++) {
            packsplit_h(S[mi][nj][0], S[mi][nj][1], phi[mi][nj][0], plo[mi][nj][0]);
            packsplit_h(S[mi][nj][2], S[mi][nj][3], phi[mi][nj][1], plo[mi][nj][1]);
        }

    // ---- O = (Ph + Pl) @ Vh ----
    float O[2][4][4];
    #pragma unroll
    for (int i = 0; i < 2; i++)
        #pragma unroll
        for (int j = 0; j < 4; j++)
            #pragma unroll
            for (int e = 0; e < 4; e++) O[i][j][e] = 0.f;

    #pragma unroll
    for (int t = 0; t < 4; t++) {
        #pragma unroll
        for (int jn = 0; jn < 4; jn++) {
            int vrow = t * 16 + (lane & 7) + ((lane >> 3) & 1) * 8;
            int vcol = hl * 32 + jn * 8;
            uint bh[2];
            ldsm_x2t(bh, VH + (uint)(vrow * 136 + vcol) * 2);
            #pragma unroll
            for (int mi = 0; mi < 2; mi++) {
                uint pa[4] = {phi[mi][2 * t][0], phi[mi][2 * t][1],
                              phi[mi][2 * t + 1][0], phi[mi][2 * t + 1][1]};
                uint la[4] = {plo[mi][2 * t][0], plo[mi][2 * t][1],
                              plo[mi][2 * t + 1][0], plo[mi][2 * t + 1][1]};
                mma16816f16(O[mi][jn], pa, bh);
                mma16816f16(O[mi][jn], la, bh);
            }
        }
    }

    __half* doh = g_oh + (size_t)bt * (64 * 256);
    #pragma unroll
    for (int mi = 0; mi < 2; mi++) {
        #pragma unroll
        for (int jn = 0; jn < 4; jn++) {
            int row = r0 + mi * 16 + g;
            int col = h * 32 + jn * 8 + tc * 2;
            *reinterpret_cast<uint*>(doh + row * 256 + col) =
                pack_h(O[mi][jn][0], O[mi][jn][1]);
            *reinterpret_cast<uint*>(doh + (row + 8) * 256 + col) =
                pack_h(O[mi][jn][2], O[mi][jn][3]);
        }
    }
}

// =============================================================================
// proj GEMM: out = Oh[M,256] @ wp^T + bias (fp32 out). Pure cp.async both
// sides, hi-only. occ 2. (R10 proven)
// =============================================================================
__global__ __launch_bounds__(256, 2) void proj_kernel(
    const __half* __restrict__ Ahg, const __half* __restrict__ Bw,
    const float* __restrict__ bias, float* __restrict__ C)
{
    constexpr int K = 256, LDT = 40, STG_H = 10240;
    extern __shared__ __half smh[];
    const uint sb = sm_u32(smh);
    const int tid = threadIdx.x;
    const int m0 = blockIdx.y * 128, n0 = blockIdx.x * 128;

    auto cp_stage = [&](int kt, int s) {
        int k0 = kt * 32;
        #pragma unroll
        for (int u = 0; u < 2; u++) {
            int f = tid + u * 256;
            int r = f >> 2, c = (f & 3) << 3;
            uint da = sb + (uint)(s * STG_H + r * LDT + c) * 2;
            uint db = sb + (uint)(s * STG_H + 5120 + r * LDT + c) * 2;
            CP16(da, Ahg + (size_t)(m0 + r) * K + k0 + c);
            CP16(db, Bw + (size_t)(n0 + r) * K + k0 + c);
        }
        CP_COMMIT();
    };

    const int warp = tid >> 5, lane = tid & 31;
    const int wm = warp & 3, wn = warp >> 2;
    const int g = lane >> 2, tc = lane & 3;

    float acc[2][8][4];
    #pragma unroll
    for (int i = 0; i < 2; i++)
        #pragma unroll
        for (int j = 0; j < 8; j++)
            #pragma unroll
            for (int e = 0; e < 4; e++) acc[i][j][e] = 0.f;

    cp_stage(0, 0);
    cp_stage(1, 1);
    CP_WAIT(0);
    __syncthreads();

    #pragma unroll
    for (int kt = 0; kt < 8; kt++) {
        const __half* st = smh + (kt & 1) * STG_H;
        const __half* Ah = st;
        const __half* Bh = st + 5120;

        #pragma unroll
        for (int kk = 0; kk < 2; kk++) {
            const int kc = kk * 16 + tc * 2;
            uint ah[2][4];
            #pragma unroll
            for (int mi = 0; mi < 2; mi++) {
                int row = wm * 32 + mi * 16 + g;
                ah[mi][0] = lds_u32(Ah + row * LDT + kc);
                ah[mi][1] = lds_u32(Ah + (row + 8) * LDT + kc);
                ah[mi][2] = lds_u32(Ah + row * LDT + kc + 8);
                ah[mi][3] = lds_u32(Ah + (row + 8) * LDT + kc + 8);
            }
            #pragma unroll
            for (int nj = 0; nj < 8; nj++) {
                int n = wn * 64 + nj * 8 + g;
                uint bh[2];
                bh[0] = lds_u32(Bh + n * LDT + kc);
                bh[1] = lds_u32(Bh + n * LDT + kc + 8);
                #pragma unroll
                for (int mi = 0; mi < 2; mi++)
                    mma16816f16(acc[mi][nj], ah[mi], bh);
            }
        }
        __syncthreads();
        if (kt < 6) { cp_stage(kt + 2, kt & 1); CP_WAIT(1); __syncthreads(); }
        else if (kt == 6) { CP_WAIT(0); __syncthreads(); }
    }

    #pragma unroll
    for (int mi = 0; mi < 2; mi++) {
        #pragma unroll
        for (int nj = 0; nj < 8; nj++) {
            int row = m0 + wm * 32 + mi * 16 + g;
            int col = n0 + wn * 64 + nj * 8 + tc * 2;
            float b0 = __ldg(bias + col), b1 = __ldg(bias + col + 1);
            *reinterpret_cast<float2*>(C + (size_t)row * 256 + col) =
                make_float2(acc[mi][nj][0] + b0, acc[mi][nj][1] + b1);
            *reinterpret_cast<float2*>(C + (size_t)(row + 8) * 256 + col) =
                make_float2(acc[mi][nj][2] + b0, acc[mi][nj][3] + b1);
        }
    }
}

// =============================================================================
extern "C" void kernel_launch(void* const* d_in, const int* in_sizes, int n_in,
                              void* d_out, int out_size)
{
    const float* x      = (const float*)d_in[0];
    const float* memory = (const float*)d_in[1];
    const float* q_w    = (const float*)d_in[2];
    const float* q_b    = (const float*)d_in[3];
    const float* kv_w   = (const float*)d_in[4];
    const float* kv_b   = (const float*)d_in[5];
    const float* proj_w = (const float*)d_in[6];
    const float* proj_b = (const float*)d_in[7];
    const float* rpb    = (const float*)d_in[8];
    float* out = (float*)d_out;

    __half *qh, *kh, *vh, *oh, *wq, *wkv, *wp;
    cudaGetSymbolAddress((void**)&qh, g_qh);
    cudaGetSymbolAddress((void**)&kh, g_kh);
    cudaGetSymbolAddress((void**)&vh, g_vh);
    cudaGetSymbolAddress((void**)&oh, g_oh);
    cudaGetSymbolAddress((void**)&wq, g_wq);
    cudaGetSymbolAddress((void**)&wkv, g_wkv);
    cudaGetSymbolAddress((void**)&wp, g_wp);

    cudaFuncSetAttribute(gemm_h_kernel,
                         cudaFuncAttributeMaxDynamicSharedMemorySize, 40960);
    cudaFuncSetAttribute(attn_kernel,
                         cudaFuncAttributeMaxDynamicSharedMemorySize, 59424);
    cudaFuncSetAttribute(proj_kernel,
                         cudaFuncAttributeMaxDynamicSharedMemorySize, 40960);

    // pre-convert weights to fp16
    wconv_kernel<<<128, 256>>>(q_w, kv_w, proj_w);
    // q projection (hi-only) -> qh
    gemm_h_kernel<<<dim3(2, 1024), 256, 40960>>>(x, wq, q_b, qh, qh);
    // kv projection (hi-only) -> kh, vh
    gemm_h_kernel<<<dim3(4, 2048), 256, 40960>>>(memory, wkv, kv_b, kh, vh);
    // fused attention -> oh
    attn_kernel<<<8192, 256, 59424>>>(rpb);
    // output projection (hi-only) -> fp32 out
    proj_kernel<<<dim3(2, 2048), 256, 40960>>>(oh, wp, proj_b, out);
}

// round 14
// speedup vs baseline: 1.6050x; 1.0392x over previous
#include <cuda_runtime.h>
#include <cuda_fp16.h>

typedef unsigned int uint;

// ---------------- scratch (device globals; no allocs allowed) ----------------
__device__ __half g_qh[2048L * 64 * 256];   // 64 MB  q hi (hi-only)
__device__ __half g_kh[4096L * 64 * 256];   // 128 MB k hi
__device__ __half g_vh[4096L * 64 * 256];   // 128 MB v hi (seq-major)
__device__ __half g_oh[4096L * 64 * 256];   // 128 MB attention out (hi only)
__device__ __half g_wq[256 * 256];          // fp16 weights (pre-converted)
__device__ __half g_wkv[512 * 256];
__device__ __half g_wp[256 * 256];

#define DEV_INLINE __device__ __forceinline__

DEV_INLINE void mma16816f16(float* d, const uint* a, const uint* b) {
    asm volatile(
        "mma.sync.aligned.m16n8k16.row.col.f32.f16.f16.f32 "
        "{%0,%1,%2,%3}, {%4,%5,%6,%7}, {%8,%9}, {%0,%1,%2,%3};\n"
        : "+f"(d[0]), "+f"(d[1]), "+f"(d[2]), "+f"(d[3])
        : "r"(a[0]), "r"(a[1]), "r"(a[2]), "r"(a[3]), "r"(b[0]), "r"(b[1]));
}

DEV_INLINE uint lds_u32(const void* p) { return *reinterpret_cast<const uint*>(p); }

DEV_INLINE uint sm_u32(const void* p) {
    uint a;
    asm("{ .reg .u64 t; cvta.to.shared.u64 t, %1; cvt.u32.u64 %0, t; }" : "=r"(a) : "l"(p));
    return a;
}

#define CP16(dst, src) \
    asm volatile("cp.async.cg.shared.global [%0], [%1], 16;" :: "r"(dst), "l"(src))
#define CP_COMMIT() asm volatile("cp.async.commit_group;" ::: "memory")
#define CP_WAIT(n)  asm volatile("cp.async.wait_group %0;" :: "n"(n) : "memory")

DEV_INLINE void ldsm_x4(uint* r, uint a) {
    asm volatile("ldmatrix.sync.aligned.m8n8.x4.shared.b16 {%0,%1,%2,%3}, [%4];"
                 : "=r"(r[0]), "=r"(r[1]), "=r"(r[2]), "=r"(r[3]) : "r"(a));
}
DEV_INLINE void ldsm_x2(uint* r, uint a) {
    asm volatile("ldmatrix.sync.aligned.m8n8.x2.shared.b16 {%0,%1}, [%2];"
                 : "=r"(r[0]), "=r"(r[1]) : "r"(a));
}
DEV_INLINE void ldsm_x2t(uint* r, uint a) {
    asm volatile("ldmatrix.sync.aligned.m8n8.x2.trans.shared.b16 {%0,%1}, [%2];"
                 : "=r"(r[0]), "=r"(r[1]) : "r"(a));
}

DEV_INLINE uint pack_h(float x, float y) {
    __half2 h = __floats2half2_rn(x, y);
    return *reinterpret_cast<uint*>(&h);
}

// =============================================================================
// weight pre-convert: fp32 -> fp16 (one shot)
// =============================================================================
__global__ __launch_bounds__(256) void wconv_kernel(
    const float* __restrict__ qw, const float* __restrict__ kvw,
    const float* __restrict__ pw)
{
    int i = (blockIdx.x * 256 + threadIdx.x) * 4;
    if (i < 65536) {
        float4 v = *reinterpret_cast<const float4*>(qw + i);
        uint2 o; o.x = pack_h(v.x, v.y); o.y = pack_h(v.z, v.w);
        *reinterpret_cast<uint2*>(g_wq + i) = o;
    }
    if (i < 131072) {
        float4 v = *reinterpret_cast<const float4*>(kvw + i);
        uint2 o; o.x = pack_h(v.x, v.y); o.y = pack_h(v.z, v.w);
        *reinterpret_cast<uint2*>(g_wkv + i) = o;
    }
    if (i < 65536) {
        float4 v = *reinterpret_cast<const float4*>(pw + i);
        uint2 o; o.x = pack_h(v.x, v.y); o.y = pack_h(v.z, v.w);
        *reinterpret_cast<uint2*>(g_wp + i) = o;
    }
}

// =============================================================================
// hi-only GEMM (serves q and kv): C = round16( A[M,256] @ Bw^T + bias ).
// A fp32 reg-pipelined; B fp16 cp.async. occ 2. Col<256 -> C1 else C2.
// (R10/R12 proven)
// =============================================================================
__global__ __launch_bounds__(256, 2) void gemm_h_kernel(
    const float* __restrict__ A, const __half* __restrict__ Bw,
    const float* __restrict__ bias, __half* __restrict__ C1,
    __half* __restrict__ C2)
{
    constexpr int K = 256, LDT = 40, STG_H = 10240;
    extern __shared__ __half smh[];
    const uint sb = sm_u32(smh);
    const int tid = threadIdx.x;
    const int m0 = blockIdx.y * 128, n0 = blockIdx.x * 128;
    const int lr = tid >> 3, lc = (tid & 7) << 2;

    float4 va0[4], va1[4];
    auto ldg_a = [&](int kt, float4 (&va)[4]) {
        int k0 = kt * 32;
        #pragma unroll
        for (int u = 0; u < 4; u++) {
            int r = lr + u * 32;
            va[u] = *reinterpret_cast<const float4*>(A + (size_t)(m0 + r) * K + k0 + lc);
        }
    };
    auto sts_a = [&](int s, const float4 (&va)[4]) {
        __half* st = smh + s * STG_H;
        #pragma unroll
        for (int u = 0; u < 4; u++) {
            int r = lr + u * 32;
            __half* hp = st + r * LDT + lc;
            *reinterpret_cast<__half2*>(hp) = __floats2half2_rn(va[u].x, va[u].y);
            *reinterpret_cast<__half2*>(hp + 2) = __floats2half2_rn(va[u].z, va[u].w);
        }
    };
    auto cp_b = [&](int kt, int s) {
        int k0 = kt * 32;
        #pragma unroll
        for (int u = 0; u < 2; u++) {
            int f = tid + u * 256;
            int r = f >> 2, c = (f & 3) << 3;
            uint dst = sb + (uint)(s * STG_H + 5120 + r * LDT + c) * 2;
            CP16(dst, Bw + (size_t)(n0 + r) * K + k0 + c);
        }
        CP_COMMIT();
    };

    const int warp = tid >> 5, lane = tid & 31;
    const int wm = warp & 3, wn = warp >> 2;
    const int g = lane >> 2, tc = lane & 3;

    float acc[2][8][4];
    #pragma unroll
    for (int i = 0; i < 2; i++)
        #pragma unroll
        for (int j = 0; j < 8; j++)
            #pragma unroll
            for (int e = 0; e < 4; e++) acc[i][j][e] = 0.f;

    cp_b(0, 0);
    cp_b(1, 1);
    ldg_a(0, va0);
    sts_a(0, va0);
    ldg_a(1, va1);
    CP_WAIT(0);
    __syncthreads();

    #pragma unroll
    for (int kt = 0; kt < 8; kt++) {
        if (kt < 6) {
            if ((kt & 1) == 0) ldg_a(kt + 2, va0);
            else               ldg_a(kt + 2, va1);
        }
        const __half* st = smh + (kt & 1) * STG_H;
        const __half* Ah = st;
        const __half* Bh = st + 5120;

        #pragma unroll
        for (int kk = 0; kk < 2; kk++) {
            const int kc = kk * 16 + tc * 2;
            uint ah[2][4];
            #pragma unroll
            for (int mi = 0; mi < 2; mi++) {
                int row = wm * 32 + mi * 16 + g;
                ah[mi][0] = lds_u32(Ah + row * LDT + kc);
                ah[mi][1] = lds_u32(Ah + (row + 8) * LDT + kc);
                ah[mi][2] = lds_u32(Ah + row * LDT + kc + 8);
                ah[mi][3] = lds_u32(Ah + (row + 8) * LDT + kc + 8);
            }
            #pragma unroll
            for (int nj = 0; nj < 8; nj++) {
                int n = wn * 64 + nj * 8 + g;
                uint bh[2];
                bh[0] = lds_u32(Bh + n * LDT + kc);
                bh[1] = lds_u32(Bh + n * LDT + kc + 8);
                #pragma unroll
                for (int mi = 0; mi < 2; mi++)
                    mma16816f16(acc[mi][nj], ah[mi], bh);
            }
        }
        __syncthreads();
        if (kt < 6) cp_b(kt + 2, kt & 1);
        if (kt < 7) {
            if (((kt + 1) & 1) == 0) sts_a((kt + 1) & 1, va0);
            else                     sts_a((kt + 1) & 1, va1);
            if (kt < 6) { CP_WAIT(1); } else { CP_WAIT(0); }
            __syncthreads();
        }
    }

    #pragma unroll
    for (int mi = 0; mi < 2; mi++) {
        #pragma unroll
        for (int nj = 0; nj < 8; nj++) {
            int row = m0 + wm * 32 + mi * 16 + g;
            int col = n0 + wn * 64 + nj * 8 + tc * 2;
            float b0 = __ldg(bias + col), b1 = __ldg(bias + col + 1);
            __half* dst = (col < 256) ? C1 : C2;
            int cc = (col < 256) ? col : col - 256;
            *reinterpret_cast<uint*>(dst + (size_t)row * 256 + cc) =
                pack_h(acc[mi][nj][0] + b0, acc[mi][nj][1] + b1);
            *reinterpret_cast<uint*>(dst + (size_t)(row + 8) * 256 + cc) =
                pack_h(acc[mi][nj][2] + b0, acc[mi][nj][3] + b1);
        }
    }
}

// =============================================================================
// Fused attention v3: instruction diet.
//  - P hi-only (O phase 32 MMA/warp, was 64)
//  - max-free softmax (logits are O(1); exp is fp32-safe)
//  - algebraic bias addressing: immediate-offset LDS off one base register
// One CTA per (bt, head-group of 4). 256 threads, smem 59424 -> 2 CTAs/SM.
// =============================================================================
__global__ __launch_bounds__(256, 2) void attn_kernel(const float* __restrict__ rpb)
{
    extern __shared__ char smc[];
    const uint sb = sm_u32(smc);
    const uint QH = sb, KH = sb + 17408, VH = sb + 34816;
    float* srpb = reinterpret_cast<float*>(smc + 52224);

    const int tid = threadIdx.x;
    const int bt = blockIdx.x >> 1;
    const int hg = blockIdx.x & 1;
    const int b = bt >> 1;

    const __half* qh_src = g_qh + (size_t)b * (64 * 256) + hg * 128;
    const __half* kh_src = g_kh + (size_t)bt * (64 * 256) + hg * 128;
    const __half* vh_src = g_vh + (size_t)bt * (64 * 256) + hg * 128;

    #pragma unroll
    for (int u = 0; u < 4; u++) {
        int f = tid + u * 256;
        int r = f >> 4;
        int cc = (f & 15) << 3;
        uint doff = (uint)(r * 136 + cc) * 2;
        size_t soff = (size_t)r * 256 + cc;
        CP16(QH + doff, qh_src + soff);
        CP16(KH + doff, kh_src + soff);
        CP16(VH + doff, vh_src + soff);
    }
    for (int i = tid; i < 450; i += 256)
        CP16(sb + 52224 + i * 16, rpb + i * 4);
    CP_COMMIT();
    CP_WAIT(0);
    __syncthreads();

    const int warp = tid >> 5, lane = tid & 31;
    const int hl = warp >> 1;
    const int h = hg * 4 + hl;
    const int half = warp & 1;
    const int g = lane >> 2, tc = lane & 3;
    const int r0 = half * 32;

    // ---- S = qh @ kh^T (hi-only) ----
    float S[2][8][4];
    #pragma unroll
    for (int i = 0; i < 2; i++)
        #pragma unroll
        for (int j = 0; j < 8; j++)
            #pragma unroll
            for (int e = 0; e < 4; e++) S[i][j][e] = 0.f;

    #pragma unroll
    for (int kk = 0; kk < 2; kk++) {
        const int kc0 = hl * 32 + kk * 16;
        uint ah[2][4];
        #pragma unroll
        for (int mi = 0; mi < 2; mi++) {
            int arow = r0 + mi * 16 + (lane & 15);
            int acol = kc0 + (lane >> 4) * 8;
            ldsm_x4(ah[mi], QH + (uint)(arow * 136 + acol) * 2);
        }
        #pragma unroll
        for (int nj = 0; nj < 8; nj++) {
            int brow = nj * 8 + (lane & 7);
            int bcol = kc0 + ((lane >> 3) & 1) * 8;
            uint bh[2];
            ldsm_x2(bh, KH + (uint)(brow * 136 + bcol) * 2);
            #pragma unroll
            for (int mi = 0; mi < 2; mi++)
                mma16816f16(S[mi][nj], ah[mi], bh);
        }
    }

    // ---- scale + bias + max-free softmax (fp32) ----
    // bias idx: rel*8+h = (rowcode+112)*8+h - (nj*15 + tc*2+e)*8,
    // rowcode = (row>>3)*15 + (row&7). Per-(mi,p) base ptr, immediate offsets.
    const float scale = 0.17677669529663687f;
    #pragma unroll
    for (int mi = 0; mi < 2; mi++) {
        #pragma unroll
        for (int p = 0; p < 2; p++) {
            int row = r0 + mi * 16 + g + p * 8;
            int rowcode = (row >> 3) * 15 + (row & 7);
            const float* bp = srpb + (rowcode + 112) * 8 + h - tc * 16;
            float sum = 0.f;
            #pragma unroll
            for (int nj = 0; nj < 8; nj++) {
                #pragma unroll
                for (int e = 0; e < 2; e++) {
                    float s = S[mi][nj][p * 2 + e] * scale + bp[-(nj * 120 + e * 8)];
                    float pe = __expf(s);
                    S[mi][nj][p * 2 + e] = pe;
                    sum += pe;
                }
            }
            sum += __shfl_xor_sync(0xffffffffu, sum, 1);
            sum += __shfl_xor_sync(0xffffffffu, sum, 2);
            float inv = 1.f / sum;
            #pragma unroll
            for (int nj = 0; nj < 8; nj++) {
                S[mi][nj][p * 2 + 0] *= inv;
                S[mi][nj][p * 2 + 1] *= inv;
            }
        }
    }

    // ---- pack P to fp16 (hi only) ----
    uint ph[2][8][2];
    #pragma unroll
    for (int mi = 0; mi < 2; mi++)
        #pragma unroll
        for (int nj = 0; nj < 8; nj++) {
            ph[mi][nj][0] = pack_h(S[mi][nj][0], S[mi][nj][1]);
            ph[mi][nj][1] = pack_h(S[mi][nj][2], S[mi][nj][3]);
        }

    // ---- O = Ph @ Vh ----
    float O[2][4][4];
    #pragma unroll
    for (int i = 0; i < 2; i++)
        #pragma unroll
        for (int j = 0; j < 4; j++)
            #pragma unroll
            for (int e = 0; e < 4; e++) O[i][j][e] = 0.f;

    #pragma unroll
    for (int t = 0; t < 4; t++) {
        #pragma unroll
        for (int jn = 0; jn < 4; jn++) {
            int vrow = t * 16 + (lane & 7) + ((lane >> 3) & 1) * 8;
            int vcol = hl * 32 + jn * 8;
            uint bh[2];
            ldsm_x2t(bh, VH + (uint)(vrow * 136 + vcol) * 2);
            #pragma unroll
            for (int mi = 0; mi < 2; mi++) {
                uint pa[4] = {ph[mi][2 * t][0], ph[mi][2 * t][1],
                              ph[mi][2 * t + 1][0], ph[mi][2 * t + 1][1]};
                mma16816f16(O[mi][jn], pa, bh);
            }
        }
    }

    __half* doh = g_oh + (size_t)bt * (64 * 256);
    #pragma unroll
    for (int mi = 0; mi < 2; mi++) {
        #pragma unroll
        for (int jn = 0; jn < 4; jn++) {
            int row = r0 + mi * 16 + g;
            int col = h * 32 + jn * 8 + tc * 2;
            *reinterpret_cast<uint*>(doh + row * 256 + col) =
                pack_h(O[mi][jn][0], O[mi][jn][1]);
            *reinterpret_cast<uint*>(doh + (row + 8) * 256 + col) =
                pack_h(O[mi][jn][2], O[mi][jn][3]);
        }
    }
}

// =============================================================================
// proj GEMM: out = Oh[M,256] @ wp^T + bias (fp32 out). Pure cp.async both
// sides, hi-only. occ 2. (R10/R12 proven)
// =============================================================================
__global__ __launch_bounds__(256, 2) void proj_kernel(
    const __half* __restrict__ Ahg, const __half* __restrict__ Bw,
    const float* __restrict__ bias, float* __restrict__ C)
{
    constexpr int K = 256, LDT = 40, STG_H = 10240;
    extern __shared__ __half smh[];
    const uint sb = sm_u32(smh);
    const int tid = threadIdx.x;
    const int m0 = blockIdx.y * 128, n0 = blockIdx.x * 128;

    auto cp_stage = [&](int kt, int s) {
        int k0 = kt * 32;
        #pragma unroll
        for (int u = 0; u < 2; u++) {
            int f = tid + u * 256;
            int r = f >> 2, c = (f & 3) << 3;
            uint da = sb + (uint)(s * STG_H + r * LDT + c) * 2;
            uint db = sb + (uint)(s * STG_H + 5120 + r * LDT + c) * 2;
            CP16(da, Ahg + (size_t)(m0 + r) * K + k0 + c);
            CP16(db, Bw + (size_t)(n0 + r) * K + k0 + c);
        }
        CP_COMMIT();
    };

    const int warp = tid >> 5, lane = tid & 31;
    const int wm = warp & 3, wn = warp >> 2;
    const int g = lane >> 2, tc = lane & 3;

    float acc[2][8][4];
    #pragma unroll
    for (int i = 0; i < 2; i++)
        #pragma unroll
        for (int j = 0; j < 8; j++)
            #pragma unroll
            for (int e = 0; e < 4; e++) acc[i][j][e] = 0.f;

    cp_stage(0, 0);
    cp_stage(1, 1);
    CP_WAIT(0);
    __syncthreads();

    #pragma unroll
    for (int kt = 0; kt < 8; kt++) {
        const __half* st = smh + (kt & 1) * STG_H;
        const __half* Ah = st;
        const __half* Bh = st + 5120;

        #pragma unroll
        for (int kk = 0; kk < 2; kk++) {
            const int kc = kk * 16 + tc * 2;
            uint ah[2][4];
            #pragma unroll
            for (int mi = 0; mi < 2; mi++) {
                int row = wm * 32 + mi * 16 + g;
                ah[mi][0] = lds_u32(Ah + row * LDT + kc);
                ah[mi][1] = lds_u32(Ah + (row + 8) * LDT + kc);
                ah[mi][2] = lds_u32(Ah + row * LDT + kc + 8);
                ah[mi][3] = lds_u32(Ah + (row + 8) * LDT + kc + 8);
            }
            #pragma unroll
            for (int nj = 0; nj < 8; nj++) {
                int n = wn * 64 + nj * 8 + g;
                uint bh[2];
                bh[0] = lds_u32(Bh + n * LDT + kc);
                bh[1] = lds_u32(Bh + n * LDT + kc + 8);
                #pragma unroll
                for (int mi = 0; mi < 2; mi++)
                    mma16816f16(acc[mi][nj], ah[mi], bh);
            }
        }
        __syncthreads();
        if (kt < 6) { cp_stage(kt + 2, kt & 1); CP_WAIT(1); __syncthreads(); }
        else if (kt == 6) { CP_WAIT(0); __syncthreads(); }
    }

    #pragma unroll
    for (int mi = 0; mi < 2; mi++) {
        #pragma unroll
        for (int nj = 0; nj < 8; nj++) {
            int row = m0 + wm * 32 + mi * 16 + g;
            int col = n0 + wn * 64 + nj * 8 + tc * 2;
            float b0 = __ldg(bias + col), b1 = __ldg(bias + col + 1);
            *reinterpret_cast<float2*>(C + (size_t)row * 256 + col) =
                make_float2(acc[mi][nj][0] + b0, acc[mi][nj][1] + b1);
            *reinterpret_cast<float2*>(C + (size_t)(row + 8) * 256 + col) =
                make_float2(acc[mi][nj][2] + b0, acc[mi][nj][3] + b1);
        }
    }
}

// =============================================================================
extern "C" void kernel_launch(void* const* d_in, const int* in_sizes, int n_in,
                              void* d_out, int out_size)
{
    const float* x      = (const float*)d_in[0];
    const float* memory = (const float*)d_in[1];
    const float* q_w    = (const float*)d_in[2];
    const float* q_b    = (const float*)d_in[3];
    const float* kv_w   = (const float*)d_in[4];
    const float* kv_b   = (const float*)d_in[5];
    const float* proj_w = (const float*)d_in[6];
    const float* proj_b = (const float*)d_in[7];
    const float* rpb    = (const float*)d_in[8];
    float* out = (float*)d_out;

    __half *qh, *kh, *vh, *oh, *wq, *wkv, *wp;
    cudaGetSymbolAddress((void**)&qh, g_qh);
    cudaGetSymbolAddress((void**)&kh, g_kh);
    cudaGetSymbolAddress((void**)&vh, g_vh);
    cudaGetSymbolAddress((void**)&oh, g_oh);
    cudaGetSymbolAddress((void**)&wq, g_wq);
    cudaGetSymbolAddress((void**)&wkv, g_wkv);
    cudaGetSymbolAddress((void**)&wp, g_wp);

    cudaFuncSetAttribute(gemm_h_kernel,
                         cudaFuncAttributeMaxDynamicSharedMemorySize, 40960);
    cudaFuncSetAttribute(attn_kernel,
                         cudaFuncAttributeMaxDynamicSharedMemorySize, 59424);
    cudaFuncSetAttribute(proj_kernel,
                         cudaFuncAttributeMaxDynamicSharedMemorySize, 40960);

    // pre-convert weights to fp16
    wconv_kernel<<<128, 256>>>(q_w, kv_w, proj_w);
    // q projection (hi-only) -> qh
    gemm_h_kernel<<<dim3(2, 1024), 256, 40960>>>(x, wq, q_b, qh, qh);
    // kv projection (hi-only) -> kh, vh
    gemm_h_kernel<<<dim3(4, 2048), 256, 40960>>>(memory, wkv, kv_b, kh, vh);
    // fused attention -> oh
    attn_kernel<<<8192, 256, 59424>>>(rpb);
    // output projection (hi-only) -> fp32 out
    proj_kernel<<<dim3(2, 2048), 256, 40960>>>(oh, wp, proj_b, out);
}